// round 3
// baseline (speedup 1.0000x reference)
#include <cuda_runtime.h>
#include <cuda_bf16.h>
#include <math.h>

// ---------------- problem constants (fixed-shape problem) ----------------
#define T_TOK 8192
#define DIM   2048
#define HID   8192
#define EPS_P 1e-4f
#define RMS_EPS 1e-5f

// ---------------- scratch (static device globals; no allocs) -------------
__device__ float g_q [(size_t)T_TOK * DIM];            // 64 MB
__device__ float g_k [(size_t)T_TOK * DIM];            // 64 MB
__device__ float g_xn[(size_t)T_TOK * DIM];            // 64 MB
__device__ float g_u [(size_t)T_TOK * 2 * HID];        // 512 MB (xn @ fc1)
__device__ float g_s [(size_t)T_TOK * HID];            // 256 MB (silu(g)*hh)
__device__ float g_z [(size_t)T_TOK * DIM];            // 64 MB
__device__ float g_nq [T_TOK];
__device__ float g_nk [T_TOK];
__device__ float g_dqk[T_TOK];
__device__ float g_a  [T_TOK];
__device__ float g_c  [T_TOK];

// ---------------- SGEMM: C[M,N] = A[M,K] @ B[K,N] (+ optional D) ----------
// 128x128 block tile, BK=8, 8x8 per thread, 256 threads, double-buffered smem.
// Requires M%128==0, N%128==0, K%8==0 (true for all shapes here).
__global__ __launch_bounds__(256, 2)
void sgemm128(const float* __restrict__ A, const float* __restrict__ B,
              const float* __restrict__ D, float* __restrict__ C,
              int M, int N, int K)
{
    __shared__ float As[2][8][128];
    __shared__ float Bs[2][8][128];

    const int tid  = threadIdx.x;
    const int trow = (tid >> 4) << 3;   // 0..120
    const int tcol = (tid & 15) << 3;   // 0..120

    const int a_row = tid >> 1;         // 0..127
    const int a_col = (tid & 1) << 2;   // 0 or 4
    const int b_row = tid >> 5;         // 0..7
    const int b_col = (tid & 31) << 2;  // 0..124

    const float* Aptr = A + (size_t)(blockIdx.y * 128 + a_row) * K + a_col;
    const float* Bptr = B + (size_t)b_row * N + (size_t)blockIdx.x * 128 + b_col;

    float acc[8][8] = {};

    // prologue: tile 0
    {
        float4 av = *(const float4*)Aptr;
        float4 bv = *(const float4*)Bptr;
        As[0][a_col + 0][a_row] = av.x;
        As[0][a_col + 1][a_row] = av.y;
        As[0][a_col + 2][a_row] = av.z;
        As[0][a_col + 3][a_row] = av.w;
        *(float4*)&Bs[0][b_row][b_col] = bv;
    }
    __syncthreads();

    int buf = 0;
    for (int kt = 8; kt <= K; kt += 8) {
        float4 av, bv;
        const bool more = (kt < K);
        if (more) {
            av = *(const float4*)(Aptr + kt);
            bv = *(const float4*)(Bptr + (size_t)kt * N);
        }
        #pragma unroll
        for (int k = 0; k < 8; ++k) {
            float4 a0 = *(const float4*)&As[buf][k][trow];
            float4 a1 = *(const float4*)&As[buf][k][trow + 4];
            float4 b0 = *(const float4*)&Bs[buf][k][tcol];
            float4 b1 = *(const float4*)&Bs[buf][k][tcol + 4];
            float af[8] = {a0.x, a0.y, a0.z, a0.w, a1.x, a1.y, a1.z, a1.w};
            float bf[8] = {b0.x, b0.y, b0.z, b0.w, b1.x, b1.y, b1.z, b1.w};
            #pragma unroll
            for (int i = 0; i < 8; ++i)
                #pragma unroll
                for (int j = 0; j < 8; ++j)
                    acc[i][j] = fmaf(af[i], bf[j], acc[i][j]);
        }
        if (more) {
            const int nb = buf ^ 1;
            As[nb][a_col + 0][a_row] = av.x;
            As[nb][a_col + 1][a_row] = av.y;
            As[nb][a_col + 2][a_row] = av.z;
            As[nb][a_col + 3][a_row] = av.w;
            *(float4*)&Bs[nb][b_row][b_col] = bv;
            __syncthreads();
            buf = nb;
        }
    }

    const size_t crow = (size_t)blockIdx.y * 128 + trow;
    const size_t ccol = (size_t)blockIdx.x * 128 + tcol;
    #pragma unroll
    for (int i = 0; i < 8; ++i) {
        size_t off = (crow + i) * (size_t)N + ccol;
        float4 v0 = make_float4(acc[i][0], acc[i][1], acc[i][2], acc[i][3]);
        float4 v1 = make_float4(acc[i][4], acc[i][5], acc[i][6], acc[i][7]);
        if (D) {
            float4 d0 = *(const float4*)(D + off);
            float4 d1 = *(const float4*)(D + off + 4);
            v0.x += d0.x; v0.y += d0.y; v0.z += d0.z; v0.w += d0.w;
            v1.x += d1.x; v1.y += d1.y; v1.z += d1.z; v1.w += d1.w;
        }
        *(float4*)(C + off)     = v0;
        *(float4*)(C + off + 4) = v1;
    }
}

// ---------------- block reduction helper ----------------
__device__ __forceinline__ float block_sum(float v, float* sm)
{
    #pragma unroll
    for (int o = 16; o > 0; o >>= 1) v += __shfl_down_sync(0xffffffffu, v, o);
    const int lane = threadIdx.x & 31, wid = threadIdx.x >> 5;
    if (lane == 0) sm[wid] = v;
    __syncthreads();
    v = (threadIdx.x < (blockDim.x >> 5)) ? sm[threadIdx.x] : 0.f;
    if (wid == 0) {
        #pragma unroll
        for (int o = 16; o > 0; o >>= 1) v += __shfl_down_sync(0xffffffffu, v, o);
    }
    return v; // valid on thread 0
}

// ---------------- rmsnorm: xn = x * rsqrt(mean(x^2)+eps) * w --------------
__global__ void rmsnorm_kernel(const float* __restrict__ x,
                               const float* __restrict__ w,
                               float* __restrict__ xn)
{
    __shared__ float sm[32];
    __shared__ float s_inv;
    const int row = blockIdx.x;
    const float* xr = x + (size_t)row * DIM;
    float ss = 0.f;
    for (int i = threadIdx.x; i < DIM; i += blockDim.x) {
        float v = xr[i];
        ss = fmaf(v, v, ss);
    }
    ss = block_sum(ss, sm);
    if (threadIdx.x == 0) s_inv = rsqrtf(ss / (float)DIM + RMS_EPS);
    __syncthreads();
    const float inv = s_inv;
    float* xo = xn + (size_t)row * DIM;
    for (int i = threadIdx.x; i < DIM; i += blockDim.x)
        xo[i] = xr[i] * inv * w[i];
}

// ------- per-token stats: |q_t|^2, |k_t|^2, q_{t-1}.k_t -------------------
__global__ void qkstats_kernel(const float* __restrict__ q,
                               const float* __restrict__ k,
                               float* __restrict__ nq2,
                               float* __restrict__ nk2,
                               float* __restrict__ dqk)
{
    __shared__ float sm[32];
    const int t = blockIdx.x;
    const float* qr = q + (size_t)t * DIM;
    const float* kr = k + (size_t)t * DIM;
    float sq = 0.f, sk = 0.f, sd = 0.f;
    for (int i = threadIdx.x; i < DIM; i += blockDim.x) {
        float qv = qr[i], kv = kr[i];
        sq = fmaf(qv, qv, sq);
        sk = fmaf(kv, kv, sk);
        if (t > 0) sd = fmaf(qr[i - DIM], kv, sd);
    }
    sq = block_sum(sq, sm);
    __syncthreads();
    sk = block_sum(sk, sm);
    __syncthreads();
    sd = block_sum(sd, sm);
    if (threadIdx.x == 0) {
        nq2[t] = sq;
        nk2[t] = sk;
        dqk[t] = (t > 0) ? sd : 0.f;
    }
}

// ------- boundary probs -> scan coefficients a_t, c_t ---------------------
__global__ void pcoef_kernel(const float* __restrict__ nq2,
                             const float* __restrict__ nk2,
                             const float* __restrict__ dqk,
                             const int* __restrict__ cu, int nseq,
                             float* __restrict__ a, float* __restrict__ c)
{
    const int t = blockIdx.x * blockDim.x + threadIdx.x;
    if (t >= T_TOK) return;
    bool ss = false;
    for (int i = 0; i < nseq; ++i) ss |= (cu[i] == t);
    float p;
    if (t == 0 || ss) {
        p = 1.0f;
    } else {
        float cosv = dqk[t] * rsqrtf(nq2[t - 1] * nk2[t]);
        p = (1.0f - cosv) * 0.5f;
    }
    p = fminf(fmaxf(p, EPS_P), 1.0f - EPS_P);
    const bool b = (p >= 0.5f);
    a[t] = (ss || t == 0) ? 0.f : (b ? 1.f - p : 1.f);
    c[t] = b ? p : 0.f;
}

// ------- SwiGLU: s = silu(u[:, h:]) * u[:, :h] ----------------------------
__global__ void swiglu_kernel(const float* __restrict__ u, float* __restrict__ s)
{
    const size_t idx = (size_t)blockIdx.x * blockDim.x + threadIdx.x; // float4 index
    const size_t total = (size_t)T_TOK * HID / 4;
    if (idx >= total) return;
    const size_t row  = idx / (HID / 4);
    const size_t col4 = idx % (HID / 4);
    const float4 hh = ((const float4*)(u + row * (size_t)(2 * HID)))[col4];
    const float4 g  = ((const float4*)(u + row * (size_t)(2 * HID) + HID))[col4];
    float4 r;
    r.x = hh.x * (g.x / (1.f + expf(-g.x)));
    r.y = hh.y * (g.y / (1.f + expf(-g.y)));
    r.z = hh.z * (g.z / (1.f + expf(-g.z)));
    r.w = hh.w * (g.w / (1.f + expf(-g.w)));
    ((float4*)s)[idx] = r;
}

// ------- segmented EMA scan: h_t = a_t h_{t-1} + c_t z_t ------------------
__global__ void ema_scan_kernel(const float* __restrict__ z,
                                const float* __restrict__ a,
                                const float* __restrict__ c,
                                const int* __restrict__ cu,
                                float* __restrict__ out)
{
    __shared__ float sa[1024];
    __shared__ float sc[1024];
    const int seg = blockIdx.y;
    const int t0 = cu[seg], t1 = cu[seg + 1];
    const int ch = blockIdx.x * blockDim.x + threadIdx.x;
    float h = 0.f;
    for (int base = t0; base < t1; base += 1024) {
        const int len = min(1024, t1 - base);
        __syncthreads();
        for (int i = threadIdx.x; i < len; i += blockDim.x) {
            sa[i] = a[base + i];
            sc[i] = c[base + i];
        }
        __syncthreads();
        for (int i = 0; i < len; ++i) {
            const size_t off = (size_t)(base + i) * DIM + ch;
            const float zv = z[off];
            h = fmaf(sa[i], h, sc[i] * zv);
            out[off] = h;
        }
    }
}

// ---------------- launch ----------------
extern "C" void kernel_launch(void* const* d_in, const int* in_sizes, int n_in,
                              void* d_out, int out_size)
{
    const float* x      = (const float*)d_in[0];
    const float* Wq     = (const float*)d_in[1];
    const float* Wk     = (const float*)d_in[2];
    const float* fc1    = (const float*)d_in[3];
    const float* fc2    = (const float*)d_in[4];
    const float* norm_w = (const float*)d_in[5];
    const int*   cu     = (const int*)d_in[6];
    float*       out    = (float*)d_out;
    const int nseq = in_sizes[6] - 1;

    float *q, *k, *xn, *u, *s, *z, *nq, *nk, *dqk, *a, *c;
    cudaGetSymbolAddress((void**)&q,   g_q);
    cudaGetSymbolAddress((void**)&k,   g_k);
    cudaGetSymbolAddress((void**)&xn,  g_xn);
    cudaGetSymbolAddress((void**)&u,   g_u);
    cudaGetSymbolAddress((void**)&s,   g_s);
    cudaGetSymbolAddress((void**)&z,   g_z);
    cudaGetSymbolAddress((void**)&nq,  g_nq);
    cudaGetSymbolAddress((void**)&nk,  g_nk);
    cudaGetSymbolAddress((void**)&dqk, g_dqk);
    cudaGetSymbolAddress((void**)&a,   g_a);
    cudaGetSymbolAddress((void**)&c,   g_c);

    // q = x @ Wq ; k = x @ Wk     [8192,2048] x [2048,2048]
    sgemm128<<<dim3(DIM / 128, T_TOK / 128), 256>>>(x, Wq, nullptr, q, T_TOK, DIM, DIM);
    sgemm128<<<dim3(DIM / 128, T_TOK / 128), 256>>>(x, Wk, nullptr, k, T_TOK, DIM, DIM);

    // boundary statistics and scan coefficients
    qkstats_kernel<<<T_TOK, 256>>>(q, k, nq, nk, dqk);
    pcoef_kernel<<<T_TOK / 256, 256>>>(nq, nk, dqk, cu, nseq, a, c);

    // xn = rmsnorm(x)
    rmsnorm_kernel<<<T_TOK, 256>>>(x, norm_w, xn);

    // u = xn @ fc1               [8192,2048] x [2048,16384]
    sgemm128<<<dim3(2 * HID / 128, T_TOK / 128), 256>>>(xn, fc1, nullptr, u, T_TOK, 2 * HID, DIM);

    // s = silu(g) * hh
    {
        const size_t total4 = (size_t)T_TOK * HID / 4;
        swiglu_kernel<<<(unsigned)((total4 + 255) / 256), 256>>>(u, s);
    }

    // z = x + s @ fc2            [8192,8192] x [8192,2048]
    sgemm128<<<dim3(DIM / 128, T_TOK / 128), 256>>>(s, fc2, x, z, T_TOK, DIM, HID);

    // segmented EMA scan -> out
    ema_scan_kernel<<<dim3(DIM / 256, nseq), 256>>>(z, a, c, cu, out);
}